// round 1
// baseline (speedup 1.0000x reference)
#include <cuda_runtime.h>

// ---------------- problem constants ----------------
#define BATCH 1024
#define C0_ 512
#define H0_ 14
#define C1_ 1024
#define H1_ 7
#define K0_ 100
#define K1_ 50
#define HW0 (H0_*H0_)   // 196
#define HW1 (H1_*H1_)   // 49
#define ROWS0 (BATCH*C0_)   // 524288
#define ROWS1 (BATCH*C1_)   // 1048576

// ---------------- scratch (no allocation allowed) ----------------
__device__ float g_pooled0[ROWS0];
__device__ float g_pooled1[ROWS1];
__device__ float g_accum[4];   // [num0, den0, num1, den1]

// ---------------- zero accumulators ----------------
__global__ void zero_accum_kernel() {
    if (threadIdx.x < 4) g_accum[threadIdx.x] = 0.0f;
}

// ---------------- fused global-avg-pool for both tensors ----------------
// warp per (b,c) row. feat0 rows: 196 floats = 49 float4 (aligned, 784B row
// stride). feat1 rows: 49 floats scalar.
__global__ void pool_kernel(const float* __restrict__ feat0,
                            const float* __restrict__ feat1) {
    const unsigned wid  = (blockIdx.x * blockDim.x + threadIdx.x) >> 5;
    const unsigned lane = threadIdx.x & 31u;

    if (wid < ROWS0) {
        const float4* src = reinterpret_cast<const float4*>(feat0) + (size_t)wid * 49;
        float4 a = src[lane];                       // floats 0..127
        float  s = a.x + a.y + a.z + a.w;
        if (lane < 17u) {                           // floats 128..195
            float4 c = src[32u + lane];
            s += c.x + c.y + c.z + c.w;
        }
        #pragma unroll
        for (int o = 16; o; o >>= 1) s += __shfl_xor_sync(0xffffffffu, s, o);
        if (lane == 0u) g_pooled0[wid] = s * (1.0f / 196.0f);
    } else {
        const unsigned r = wid - ROWS0;
        if (r >= ROWS1) return;
        const float* src = feat1 + (size_t)r * 49;
        float s = src[lane];
        if (lane < 17u) s += src[32u + lane];
        #pragma unroll
        for (int o = 16; o; o >>= 1) s += __shfl_xor_sync(0xffffffffu, s, o);
        if (lane == 0u) g_pooled1[r] = s * (1.0f / 49.0f);
    }
}

// ---------------- head: logits + weighted CE, accumulate into g_accum ----------------
// Block handles BTILE batch rows. Pooled tile in smem (padded, conflict-free).
// Thread (b = tid%BTILE, k = tid/BTILE + j*stride) computes one logit per j.
// Then one warp per row does softmax-CE with shfl reductions.
template<int C, int K, int BTILE, int WHICH, int AOFF>
__global__ void head_kernel(const float* __restrict__ W,
                            const float* __restrict__ bias,
                            const int*   __restrict__ lut,
                            const float* __restrict__ cw,
                            const int*   __restrict__ target) {
    __shared__ float sp[BTILE][C + 1];
    __shared__ float ls[BTILE][K];

    const float* pooled = (WHICH == 0) ? g_pooled0 : g_pooled1;
    const int b0  = blockIdx.x * BTILE;
    const int tid = threadIdx.x;
    const int nthreads = blockDim.x;

    // stage pooled tile (coalesced)
    for (int i = tid; i < BTILE * C; i += nthreads) {
        int b = i / C, c = i % C;
        sp[b][c] = pooled[(size_t)(b0 + b) * C + c];
    }
    __syncthreads();

    // logits
    {
        const int b = tid % BTILE;
        const int kstride = nthreads / BTILE;
        for (int k = tid / BTILE; k < K; k += kstride) {
            const float* __restrict__ wrow = W + (size_t)k * C;
            float acc = 0.0f;
            #pragma unroll 8
            for (int c = 0; c < C; ++c)
                acc = fmaf(sp[b][c], wrow[c], acc);
            ls[b][k] = acc + bias[k];
        }
    }
    __syncthreads();

    // softmax + weighted NLL per row (one warp per row)
    const int wid = tid >> 5, lane = tid & 31;
    const int nwarps = nthreads >> 5;
    for (int r = wid; r < BTILE; r += nwarps) {
        float m = -3.4e38f;
        for (int k = lane; k < K; k += 32) m = fmaxf(m, ls[r][k]);
        #pragma unroll
        for (int o = 16; o; o >>= 1) m = fmaxf(m, __shfl_xor_sync(0xffffffffu, m, o));
        float s = 0.0f;
        for (int k = lane; k < K; k += 32) s += __expf(ls[r][k] - m);
        #pragma unroll
        for (int o = 16; o; o >>= 1) s += __shfl_xor_sync(0xffffffffu, s, o);
        if (lane == 0) {
            const int t  = lut[target[b0 + r]];
            const float nll = m + __logf(s) - ls[r][t];
            const float w   = cw[t];
            atomicAdd(&g_accum[AOFF],     w * nll);
            atomicAdd(&g_accum[AOFF + 1], w);
        }
    }
}

// ---------------- finalize ----------------
__global__ void finalize_kernel(float* __restrict__ out) {
    out[0] = g_accum[0] / g_accum[1] + g_accum[2] / g_accum[3];
}

// ---------------- launch ----------------
extern "C" void kernel_launch(void* const* d_in, const int* in_sizes, int n_in,
                              void* d_out, int out_size) {
    (void)in_sizes; (void)n_in; (void)out_size;
    const float* feat0  = (const float*)d_in[0];
    const float* feat1  = (const float*)d_in[1];
    const float* W0     = (const float*)d_in[2];
    const float* b0     = (const float*)d_in[3];
    const float* W1     = (const float*)d_in[4];
    const float* b1     = (const float*)d_in[5];
    const int*   lut0   = (const int*)d_in[6];
    const int*   lut1   = (const int*)d_in[7];
    const float* cw0    = (const float*)d_in[8];
    const float* cw1    = (const float*)d_in[9];
    const int*   target = (const int*)d_in[10];
    float* out = (float*)d_out;

    zero_accum_kernel<<<1, 32>>>();

    // total warps = ROWS0 + ROWS1 = 1,572,864 ; 8 warps/block
    const int total_warps = ROWS0 + ROWS1;
    const int pool_blocks = (total_warps * 32 + 255) / 256;
    pool_kernel<<<pool_blocks, 256>>>(feat0, feat1);

    head_kernel<C0_, K0_, 8, 0, 0><<<BATCH / 8, 256>>>(W0, b0, lut0, cw0, target);
    head_kernel<C1_, K1_, 8, 1, 2><<<BATCH / 8, 256>>>(W1, b1, lut1, cw1, target);

    finalize_kernel<<<1, 1>>>(out);
}

// round 2
// speedup vs baseline: 2.0089x; 2.0089x over previous
#include <cuda_runtime.h>

// ---------------- problem constants ----------------
#define BATCH 1024
#define C0_ 512
#define H0_ 14
#define C1_ 1024
#define H1_ 7
#define K0_ 100
#define K1_ 50
#define ROWS0 (BATCH*C0_)   // 524288
#define ROWS1 (BATCH*C1_)   // 1048576

// ---------------- scratch (no allocation allowed) ----------------
__device__ float g_pooled0[ROWS0];
__device__ float g_pooled1[ROWS1];
__device__ float g_accum[4];   // [num0, den0, num1, den1]

// ---------------- zero accumulators ----------------
__global__ void zero_accum_kernel() {
    if (threadIdx.x < 4) g_accum[threadIdx.x] = 0.0f;
}

// ---------------- pool feat0: warp per (b,c) row, 49 float4 per row --------
__global__ void pool0_kernel(const float* __restrict__ feat0) {
    const unsigned wid  = (blockIdx.x * blockDim.x + threadIdx.x) >> 5;
    const unsigned lane = threadIdx.x & 31u;
    if (wid >= ROWS0) return;
    const float4* src = reinterpret_cast<const float4*>(feat0) + (size_t)wid * 49;
    float4 a = __ldcs(src + lane);
    float  s = a.x + a.y + a.z + a.w;
    if (lane < 17u) {
        float4 c = __ldcs(src + 32u + lane);
        s += c.x + c.y + c.z + c.w;
    }
    #pragma unroll
    for (int o = 16; o; o >>= 1) s += __shfl_xor_sync(0xffffffffu, s, o);
    if (lane == 0u) g_pooled0[wid] = s * (1.0f / 196.0f);
}

// ---------------- pool feat1: block tiles 256 rows via smem ----------------
// 256 rows x 49 floats = 12544 floats = 3136 float4 (16B-aligned since
// 256*196B = 50176B per block, multiple of 16). Coalesced vector loads,
// then thread-per-row smem sum (bank (17t+e) mod 32 -> conflict-free).
#define P1_RPB 256
#define P1_FLT (P1_RPB*49)      // 12544
#define P1_VEC (P1_FLT/4)       // 3136
__global__ void pool1_kernel(const float* __restrict__ feat1) {
    __shared__ float sf[P1_FLT];
    const size_t base = (size_t)blockIdx.x * P1_FLT;
    const float4* src = reinterpret_cast<const float4*>(feat1 + base);
    float4* dst = reinterpret_cast<float4*>(sf);
    for (int i = threadIdx.x; i < P1_VEC; i += blockDim.x)
        dst[i] = __ldcs(src + i);
    __syncthreads();
    const int t = threadIdx.x;
    const float* r = sf + t * 49;
    float s0 = 0.f, s1 = 0.f, s2 = 0.f, s3 = 0.f;
    #pragma unroll
    for (int e = 0; e < 48; e += 4) {
        s0 += r[e]; s1 += r[e+1]; s2 += r[e+2]; s3 += r[e+3];
    }
    const float s = s0 + s1 + s2 + s3 + r[48];
    g_pooled1[(size_t)blockIdx.x * P1_RPB + t] = s * (1.0f / 49.0f);
}

// ---------------- fused heads: one warp per batch row ----------------------
// Pooled row lives in registers (C/32 per lane). For each k: coalesced 128B
// loads of W row + register FMA + 5-shfl reduce; logits staged in smem;
// warp softmax-CE; lane0 atomically accumulates weighted num/den.
template<int C, int K, int AOFF>
__device__ __forceinline__ void head_row(
    int b, int lane, float* __restrict__ slg,
    const float* __restrict__ pooled,
    const float* __restrict__ W, const float* __restrict__ bias,
    const int* __restrict__ lut, const float* __restrict__ cw,
    const int* __restrict__ target)
{
    constexpr int NR = C / 32;
    float p[NR];
    const float* pr = pooled + (size_t)b * C + lane;
    #pragma unroll
    for (int i = 0; i < NR; i++) p[i] = pr[i * 32];

    #pragma unroll 2
    for (int k = 0; k < K; k++) {
        const float* __restrict__ wr = W + (size_t)k * C + lane;
        float acc = 0.0f;
        #pragma unroll
        for (int i = 0; i < NR; i++) acc = fmaf(p[i], __ldg(wr + i * 32), acc);
        #pragma unroll
        for (int o = 16; o; o >>= 1) acc += __shfl_xor_sync(0xffffffffu, acc, o);
        if (lane == 0) slg[k] = acc + bias[k];
    }
    __syncwarp();

    float m = -3.4e38f;
    for (int k = lane; k < K; k += 32) m = fmaxf(m, slg[k]);
    #pragma unroll
    for (int o = 16; o; o >>= 1) m = fmaxf(m, __shfl_xor_sync(0xffffffffu, m, o));
    float s = 0.0f;
    for (int k = lane; k < K; k += 32) s += __expf(slg[k] - m);
    #pragma unroll
    for (int o = 16; o; o >>= 1) s += __shfl_xor_sync(0xffffffffu, s, o);

    if (lane == 0) {
        const int   t   = lut[target[b]];
        const float nll = m + __logf(s) - slg[t];
        const float wt  = cw[t];
        atomicAdd(&g_accum[AOFF],     wt * nll);
        atomicAdd(&g_accum[AOFF + 1], wt);
    }
}

__global__ void heads_kernel(
    const float* __restrict__ W0, const float* __restrict__ b0v,
    const int* __restrict__ lut0, const float* __restrict__ cw0,
    const float* __restrict__ W1, const float* __restrict__ b1v,
    const int* __restrict__ lut1, const float* __restrict__ cw1,
    const int* __restrict__ target)
{
    __shared__ float slg[4][104];
    const int gw   = (blockIdx.x * blockDim.x + threadIdx.x) >> 5;
    const int w    = threadIdx.x >> 5;
    const int lane = threadIdx.x & 31;
    if (gw < BATCH)
        head_row<C0_, K0_, 0>(gw, lane, slg[w], g_pooled0,
                              W0, b0v, lut0, cw0, target);
    else
        head_row<C1_, K1_, 2>(gw - BATCH, lane, slg[w], g_pooled1,
                              W1, b1v, lut1, cw1, target);
}

// ---------------- finalize ----------------
__global__ void finalize_kernel(float* __restrict__ out) {
    out[0] = g_accum[0] / g_accum[1] + g_accum[2] / g_accum[3];
}

// ---------------- launch ----------------
extern "C" void kernel_launch(void* const* d_in, const int* in_sizes, int n_in,
                              void* d_out, int out_size) {
    (void)in_sizes; (void)n_in; (void)out_size;
    const float* feat0  = (const float*)d_in[0];
    const float* feat1  = (const float*)d_in[1];
    const float* W0     = (const float*)d_in[2];
    const float* b0v    = (const float*)d_in[3];
    const float* W1     = (const float*)d_in[4];
    const float* b1v    = (const float*)d_in[5];
    const int*   lut0   = (const int*)d_in[6];
    const int*   lut1   = (const int*)d_in[7];
    const float* cw0    = (const float*)d_in[8];
    const float* cw1    = (const float*)d_in[9];
    const int*   target = (const int*)d_in[10];
    float* out = (float*)d_out;

    zero_accum_kernel<<<1, 32>>>();

    // feat0: warp per row
    pool0_kernel<<<(ROWS0 * 32) / 256, 256>>>(feat0);
    // feat1: 256 rows per block
    pool1_kernel<<<ROWS1 / P1_RPB, P1_RPB>>>(feat1);

    // 2048 rows total, 1 warp each, 4 warps/block -> 512 blocks
    heads_kernel<<<(2 * BATCH) / 4, 128>>>(W0, b0v, lut0, cw0,
                                           W1, b1v, lut1, cw1, target);

    finalize_kernel<<<1, 1>>>(out);
}